// round 1
// baseline (speedup 1.0000x reference)
#include <cuda_runtime.h>
#include <cstdint>

// Problem constants
#define TSTEPS 8
#define NB 64
#define NS 32
#define NBS 2048          // B*S
#define NK 3136           // DS == DT
#define NF 512
#define NH 512
#define NL 18
#define KSB 14            // split-K factor for basal GEMM
#define KCH_B 224         // 3136 / 14, multiple of 16
#define KSH 4             // split-K factor for h GEMM
#define KCH_H 128         // 512 / 4

// ---------------- scratch (__device__ globals; no allocation allowed) -------
__device__ float g_apical[TSTEPS * NBS * NF];        // 33.5 MB
__device__ float g_bpart[KSB * TSTEPS * NB * NF];    // 14.7 MB
__device__ float g_basal[TSTEPS * NB * NF];          // 1 MB
__device__ float g_mb[NB * NF];
__device__ float g_ma[NBS * NF];                     // 4 MB
__device__ float g_ms[NBS * NF];                     // 4 MB
__device__ float g_sp[NBS * NF];                     // 4 MB
__device__ float g_hpart[KSH * NBS * NH];            // 16.8 MB
__device__ float g_ml[NBS * NH];                     // 4 MB
__device__ float g_acc[NBS * NL];

// ---------------- fp32 tiled GEMM: C[z] += A[:,kslice] * B[:,kslice]^T ------
// A: [M,K] row-major, B: [N,K] row-major (both K-contiguous).
// blockIdx.z selects K-chunk; partial written to C + z*M*N (fixed-order
// reduction later => deterministic). All dims divide tiles exactly.
#define BM 128
#define BN 128
#define BKK 16
#define TM 8
#define TN 8

__global__ void __launch_bounds__(256, 2)
sgemm_nt(const float* __restrict__ A, const float* __restrict__ B,
         float* __restrict__ C, int M, int N, int K, int kChunk)
{
    __shared__ float As[BKK][BM];
    __shared__ float Bs[BKK][BN];

    const int tid    = threadIdx.x;
    const int brow   = blockIdx.y * BM;
    const int bcol   = blockIdx.x * BN;
    const int kBegin = blockIdx.z * kChunk;
    const int kEnd   = kBegin + kChunk;

    const int tx = tid & 15;      // N direction (8 cols each)
    const int ty = tid >> 4;      // M direction (8 rows each)

    const int lrow = tid >> 2;          // 0..63
    const int lcol = (tid & 3) << 2;    // 0,4,8,12

    const float* Ap = A + (size_t)(brow + lrow) * K + lcol;
    const float* Bp = B + (size_t)(bcol + lrow) * K + lcol;

    float acc[TM][TN];
#pragma unroll
    for (int i = 0; i < TM; i++)
#pragma unroll
        for (int j = 0; j < TN; j++) acc[i][j] = 0.f;

    // stage first tile
    {
        float4 a0 = *(const float4*)(Ap + kBegin);
        float4 a1 = *(const float4*)(Ap + (size_t)64 * K + kBegin);
        float4 b0 = *(const float4*)(Bp + kBegin);
        float4 b1 = *(const float4*)(Bp + (size_t)64 * K + kBegin);
        As[lcol+0][lrow]    = a0.x; As[lcol+1][lrow]    = a0.y;
        As[lcol+2][lrow]    = a0.z; As[lcol+3][lrow]    = a0.w;
        As[lcol+0][lrow+64] = a1.x; As[lcol+1][lrow+64] = a1.y;
        As[lcol+2][lrow+64] = a1.z; As[lcol+3][lrow+64] = a1.w;
        Bs[lcol+0][lrow]    = b0.x; Bs[lcol+1][lrow]    = b0.y;
        Bs[lcol+2][lrow]    = b0.z; Bs[lcol+3][lrow]    = b0.w;
        Bs[lcol+0][lrow+64] = b1.x; Bs[lcol+1][lrow+64] = b1.y;
        Bs[lcol+2][lrow+64] = b1.z; Bs[lcol+3][lrow+64] = b1.w;
    }
    __syncthreads();

    int k0 = kBegin;
    for (;;) {
        const int kn = k0 + BKK;
        const bool more = kn < kEnd;
        float4 na0, na1, nb0, nb1;
        if (more) {   // prefetch next tile into registers while computing
            na0 = *(const float4*)(Ap + kn);
            na1 = *(const float4*)(Ap + (size_t)64 * K + kn);
            nb0 = *(const float4*)(Bp + kn);
            nb1 = *(const float4*)(Bp + (size_t)64 * K + kn);
        }
#pragma unroll
        for (int kk = 0; kk < BKK; kk++) {
            float af[TM], bf[TN];
#pragma unroll
            for (int i = 0; i < TM; i++) af[i] = As[kk][ty * TM + i];
#pragma unroll
            for (int j = 0; j < TN; j++) bf[j] = Bs[kk][tx * TN + j];
#pragma unroll
            for (int i = 0; i < TM; i++)
#pragma unroll
                for (int j = 0; j < TN; j++) acc[i][j] += af[i] * bf[j];
        }
        if (!more) break;
        __syncthreads();
        As[lcol+0][lrow]    = na0.x; As[lcol+1][lrow]    = na0.y;
        As[lcol+2][lrow]    = na0.z; As[lcol+3][lrow]    = na0.w;
        As[lcol+0][lrow+64] = na1.x; As[lcol+1][lrow+64] = na1.y;
        As[lcol+2][lrow+64] = na1.z; As[lcol+3][lrow+64] = na1.w;
        Bs[lcol+0][lrow]    = nb0.x; Bs[lcol+1][lrow]    = nb0.y;
        Bs[lcol+2][lrow]    = nb0.z; Bs[lcol+3][lrow]    = nb0.w;
        Bs[lcol+0][lrow+64] = nb1.x; Bs[lcol+1][lrow+64] = nb1.y;
        Bs[lcol+2][lrow+64] = nb1.z; Bs[lcol+3][lrow+64] = nb1.w;
        __syncthreads();
        k0 = kn;
    }

    float* Cb = C + (size_t)blockIdx.z * M * N;
#pragma unroll
    for (int i = 0; i < TM; i++) {
        float* Cr = Cb + (size_t)(brow + ty * TM + i) * N + (bcol + tx * TN);
        *(float4*)(Cr)     = make_float4(acc[i][0], acc[i][1], acc[i][2], acc[i][3]);
        *(float4*)(Cr + 4) = make_float4(acc[i][4], acc[i][5], acc[i][6], acc[i][7]);
    }
}

// ---------------- state init (captured node => every replay resets) ---------
__global__ void init_state()
{
    const int i = blockIdx.x * blockDim.x + threadIdx.x;
    if (i < NBS * NF) { g_ma[i] = 0.f; g_ms[i] = 0.f; g_ml[i] = 0.f; }
    if (i < NB * NF)  g_mb[i] = 0.f;
    if (i < NBS * NL) g_acc[i] = 0.f;
}

// ---------------- basal split-K reduce (fixed order, deterministic) ---------
__global__ void reduce_basal()
{
    const int i = blockIdx.x * blockDim.x + threadIdx.x;
    if (i >= TSTEPS * NB * NF) return;
    float s = 0.f;
#pragma unroll
    for (int p = 0; p < KSB; p++) s += g_bpart[(size_t)p * (TSTEPS * NB * NF) + i];
    g_basal[i] = s;
}

// ---------------- per-step membrane kernels --------------------------------
__global__ void mb_update(int t)
{
    const int i = blockIdx.x * blockDim.x + threadIdx.x;
    if (i < NB * NF) {
        float v = g_mb[i];
        g_mb[i] = v + (g_basal[t * NB * NF + i] - v) * 0.5f;
    }
}

// ma += (apical-ma)/2 ; ms += (ma+mb-ms)/2 ; spike; hard reset. float4 wide.
__global__ void mc_spike(int t)
{
    const int i = blockIdx.x * blockDim.x + threadIdx.x;   // over NBS*NF/4
    if (i >= NBS * NF / 4) return;
    const int e = i * 4;
    const int f = e & (NF - 1);       // NF = 512
    const int b = e >> 14;            // e / (NS*NF) = e / 16384
    float4 ap  = ((const float4*)(g_apical + (size_t)t * NBS * NF))[i];
    float4 mav = ((const float4*)g_ma)[i];
    float4 msv = ((const float4*)g_ms)[i];
    float4 mbv = *(const float4*)(g_mb + b * NF + f);
    float4 spv;

    mav.x += (ap.x - mav.x) * 0.5f;
    msv.x += (mav.x + mbv.x - msv.x) * 0.5f;
    spv.x = (msv.x > 1.0f) ? 1.f : 0.f;  msv.x *= (1.f - spv.x);

    mav.y += (ap.y - mav.y) * 0.5f;
    msv.y += (mav.y + mbv.y - msv.y) * 0.5f;
    spv.y = (msv.y > 1.0f) ? 1.f : 0.f;  msv.y *= (1.f - spv.y);

    mav.z += (ap.z - mav.z) * 0.5f;
    msv.z += (mav.z + mbv.z - msv.z) * 0.5f;
    spv.z = (msv.z > 1.0f) ? 1.f : 0.f;  msv.z *= (1.f - spv.z);

    mav.w += (ap.w - mav.w) * 0.5f;
    msv.w += (mav.w + mbv.w - msv.w) * 0.5f;
    spv.w = (msv.w > 1.0f) ? 1.f : 0.f;  msv.w *= (1.f - spv.w);

    ((float4*)g_ma)[i] = mav;
    ((float4*)g_ms)[i] = msv;
    ((float4*)g_sp)[i] = spv;
}

// ---------------- fused: h-partials reduce + LIF + 18-wide readout ----------
// One warp per row r: h = b1 + sum_p hpart[p][r,:]; LIF update; for spiking
// units accumulate W2 columns; warp-reduce 18 outputs; acc[r,:] += result.
__global__ void lif_out(const float* __restrict__ b1, const float* __restrict__ W2)
{
    const int gw   = (blockIdx.x * blockDim.x + threadIdx.x) >> 5;
    const int lane = threadIdx.x & 31;
    if (gw >= NBS) return;
    float a[NL];
#pragma unroll
    for (int l = 0; l < NL; l++) a[l] = 0.f;
    const size_t base = (size_t)gw * NH;
#pragma unroll 4
    for (int j = 0; j < NH / 32; j++) {
        const int k = j * 32 + lane;
        const size_t idx = base + k;
        float h = b1[k];
#pragma unroll
        for (int p = 0; p < KSH; p++) h += g_hpart[(size_t)p * NBS * NH + idx];
        float m = g_ml[idx];
        m += (h - m) * 0.5f;
        const float s = (m > 0.5f) ? 1.f : 0.f;
        g_ml[idx] = m * (1.f - s);
        if (s != 0.f) {
#pragma unroll
            for (int l = 0; l < NL; l++) a[l] += W2[l * NH + k];
        }
    }
#pragma unroll
    for (int l = 0; l < NL; l++) {
#pragma unroll
        for (int o = 16; o; o >>= 1) a[l] += __shfl_xor_sync(0xffffffffu, a[l], o);
    }
    if (lane == 0) {
#pragma unroll
        for (int l = 0; l < NL; l++) g_acc[gw * NL + l] += a[l];
    }
}

// ---------------- final: mean over T, add b2, reorder to [B, L, S] ----------
__global__ void finalize(const float* __restrict__ b2, float* __restrict__ out)
{
    const int i = blockIdx.x * blockDim.x + threadIdx.x;
    if (i >= NB * NL * NS) return;
    const int s = i % NS;
    const int l = (i / NS) % NL;
    const int b = i / (NS * NL);
    out[i] = g_acc[(b * NS + s) * NL + l] * (1.f / TSTEPS) + b2[l];
}

// ---------------------------------------------------------------------------
extern "C" void kernel_launch(void* const* d_in, const int* in_sizes, int n_in,
                              void* d_out, int out_size)
{
    (void)in_sizes; (void)n_in; (void)out_size;
    const float* se = (const float*)d_in[0];  // [T, B, DS]
    const float* te = (const float*)d_in[1];  // [T, B*S, DT]
    const float* Wb = (const float*)d_in[2];  // [F, DS]
    const float* Wa = (const float*)d_in[3];  // [F, DT]
    const float* W1 = (const float*)d_in[4];  // [H, F]
    const float* b1 = (const float*)d_in[5];  // [H]
    const float* W2 = (const float*)d_in[6];  // [L, H]
    const float* b2 = (const float*)d_in[7];  // [L]
    float* out = (float*)d_out;               // [B, L, S]

    float *apical, *bpart, *sp, *hpart;
    cudaGetSymbolAddress((void**)&apical, g_apical);
    cudaGetSymbolAddress((void**)&bpart,  g_bpart);
    cudaGetSymbolAddress((void**)&sp,     g_sp);
    cudaGetSymbolAddress((void**)&hpart,  g_hpart);

    // reset recurrent state + accumulator (part of the graph => deterministic)
    init_state<<<(NBS * NF + 255) / 256, 256>>>();

    // hoisted GEMMs: apical for all T at once; basal with split-K=14
    sgemm_nt<<<dim3(NF / BN, (TSTEPS * NBS) / BM, 1), 256>>>(
        te, Wa, apical, TSTEPS * NBS, NF, NK, NK);
    sgemm_nt<<<dim3(NF / BN, (TSTEPS * NB) / BM, KSB), 256>>>(
        se, Wb, bpart, TSTEPS * NB, NF, NK, KCH_B);
    reduce_basal<<<(TSTEPS * NB * NF + 255) / 256, 256>>>();

    for (int t = 0; t < TSTEPS; t++) {
        mb_update<<<(NB * NF + 255) / 256, 256>>>(t);
        mc_spike<<<(NBS * NF / 4 + 255) / 256, 256>>>(t);
        sgemm_nt<<<dim3(NH / BN, NBS / BM, KSH), 256>>>(
            sp, W1, hpart, NBS, NH, NF, KCH_H);
        lif_out<<<(NBS * 32 + 255) / 256, 256>>>(b1, W2);
    }

    finalize<<<(NB * NL * NS + 255) / 256, 256>>>(b2, out);
}

// round 3
// speedup vs baseline: 1.5640x; 1.5640x over previous
#include <cuda_runtime.h>
#include <cuda_bf16.h>
#include <cstdint>

// Problem constants
#define TSTEPS 8
#define NB 64
#define NS 32
#define NBS 2048          // B*S
#define NK 3136           // DS == DT
#define NF 512
#define NH 512
#define NL 18
#define KSB 14            // split-K factor for basal GEMM (fp32 path)
#define KCH_B 224         // 3136 / 14
#define KSH 2             // split-K for h GEMM (bf16 path)

// ---------------- scratch (__device__ globals; no allocation allowed) -------
__device__ float g_apical[TSTEPS * NBS * NF];        // 33.5 MB
__device__ float g_bpart[KSB * TSTEPS * NB * NF];
__device__ float g_basal[TSTEPS * NB * NF];
__device__ float g_mb[NB * NF];
__device__ float g_ma[NBS * NF];
__device__ float g_ms[NBS * NF];
__device__ __align__(16) __nv_bfloat16 g_sp16[NBS * NF];   // spikes (exact bf16)
__device__ float g_hpart[KSH * NBS * NH];
__device__ float g_ml[NBS * NH];
__device__ float g_acc[NBS * NL];
// bf16 hi/lo splits
__device__ __align__(16) __nv_bfloat16 g_teh[TSTEPS * NBS * NK];
__device__ __align__(16) __nv_bfloat16 g_tel[TSTEPS * NBS * NK];
__device__ __align__(16) __nv_bfloat16 g_Wah[NF * NK];
__device__ __align__(16) __nv_bfloat16 g_Wal[NF * NK];
__device__ __align__(16) __nv_bfloat16 g_W1h[NH * NF];
__device__ __align__(16) __nv_bfloat16 g_W1l[NH * NF];

// ============================ PTX helpers ==================================
__device__ __forceinline__ uint32_t s2u(const void* p) {
    uint32_t a;
    asm("{ .reg .u64 t; cvta.to.shared.u64 t, %1; cvt.u32.u64 %0, t; }"
        : "=r"(a) : "l"(p));
    return a;
}
__device__ __forceinline__ void cp16(uint32_t s, const void* g) {
    asm volatile("cp.async.cg.shared.global [%0], [%1], 16;" :: "r"(s), "l"(g) : "memory");
}
__device__ __forceinline__ void cp_commit() {
    asm volatile("cp.async.commit_group;" ::: "memory");
}
__device__ __forceinline__ void cp_wait1() {
    asm volatile("cp.async.wait_group 1;" ::: "memory");
}
__device__ __forceinline__ void ldmx4(uint32_t* r, uint32_t a) {
    asm volatile("ldmatrix.sync.aligned.m8n8.x4.shared.b16 {%0,%1,%2,%3}, [%4];"
                 : "=r"(r[0]), "=r"(r[1]), "=r"(r[2]), "=r"(r[3]) : "r"(a));
}
__device__ __forceinline__ void hmma(float* c, const uint32_t* a, const uint32_t* b) {
    asm volatile(
        "mma.sync.aligned.m16n8k16.row.col.f32.bf16.bf16.f32 "
        "{%0,%1,%2,%3}, {%4,%5,%6,%7}, {%8,%9}, {%0,%1,%2,%3};"
        : "+f"(c[0]), "+f"(c[1]), "+f"(c[2]), "+f"(c[3])
        : "r"(a[0]), "r"(a[1]), "r"(a[2]), "r"(a[3]), "r"(b[0]), "r"(b[1]));
}

// ================= bf16 multi-pass HMMA GEMM ================================
// C[z] (+)= sum over passes p of A_p[M,K] * B_p[N,K]^T   (both K-contiguous)
// CTA 128x128, BK=32, 256 threads (8 warps: 4 in M x 2 in N, warp tile 32x64),
// 3-stage cp.async pipeline, fp32 accum in registers. Partial for K-slice z
// written to C + z*M*Ntot (fixed-order reduce later => deterministic).
#define BKT 32
#define NSTG 3

__global__ void __launch_bounds__(256, 1)
hmma_gemm(const __nv_bfloat16* __restrict__ A0, const __nv_bfloat16* __restrict__ B0,
          const __nv_bfloat16* __restrict__ A1, const __nv_bfloat16* __restrict__ B1,
          const __nv_bfloat16* __restrict__ A2, const __nv_bfloat16* __restrict__ B2,
          int npass, int kChunk, int lda, int Ntot, float* __restrict__ C, int M)
{
    __shared__ __nv_bfloat16 sA[NSTG][128 * BKT];
    __shared__ __nv_bfloat16 sB[NSTG][128 * BKT];

    const int tid  = threadIdx.x;
    const int wid  = tid >> 5;
    const int lane = tid & 31;
    const int wm   = wid & 3;        // warp row (0..3) -> 32 rows each
    const int wn   = wid >> 2;       // warp col (0..1) -> 64 cols each

    const int rowBase = blockIdx.y * 128;
    const int colBase = blockIdx.x * 128;
    const int kOff    = blockIdx.z * kChunk;
    const int ktpp    = kChunk / BKT;      // k-tiles per pass
    const int NT      = npass * ktpp;

    float acc[2][8][4];
#pragma unroll
    for (int mi = 0; mi < 2; mi++)
#pragma unroll
        for (int nj = 0; nj < 8; nj++)
#pragma unroll
            for (int q = 0; q < 4; q++) acc[mi][nj][q] = 0.f;

    // ---- stage issue: 4 cp.async(16B) per thread ----
    auto issue = [&](int kt) {
        const int s  = kt % NSTG;
        const int p  = kt / ktpp;
        const int kl = (kt - p * ktpp) * BKT + kOff;
        const __nv_bfloat16* Ap = (p == 0) ? A0 : ((p == 1) ? A1 : A2);
        const __nv_bfloat16* Bp = (p == 0) ? B0 : ((p == 1) ? B1 : B2);
        const uint32_t sa = s2u(&sA[s][0]);
        const uint32_t sb = s2u(&sB[s][0]);
#pragma unroll
        for (int i = 0; i < 2; i++) {
            const int v = tid + i * 256;          // 0..511
            const int m = v >> 2, u = v & 3;
            const uint32_t so = m * 64 + ((u ^ ((m >> 1) & 3)) << 4);
            cp16(sa + so, Ap + (size_t)(rowBase + m) * lda + kl + u * 8);
            cp16(sb + so, Bp + (size_t)(colBase + m) * lda + kl + u * 8);
        }
    };

    // ---- compute one BK=32 stage ----
    auto compute = [&](int s) {
        const uint32_t sa = s2u(&sA[s][0]);
        const uint32_t sb = s2u(&sB[s][0]);
#pragma unroll
        for (int k16 = 0; k16 < 2; k16++) {
            uint32_t a[2][4], b[4][4];
#pragma unroll
            for (int mi = 0; mi < 2; mi++) {
                const int row = wm * 32 + mi * 16 + (lane & 15);
                const int u   = k16 * 2 + (lane >> 4);
                ldmx4(a[mi], sa + row * 64 + ((u ^ ((row >> 1) & 3)) << 4));
            }
#pragma unroll
            for (int np = 0; np < 4; np++) {
                const int n = wn * 64 + np * 16 + ((lane >> 4) << 3) + (lane & 7);
                const int u = k16 * 2 + ((lane >> 3) & 1);
                ldmx4(b[np], sb + n * 64 + ((u ^ ((n >> 1) & 3)) << 4));
            }
#pragma unroll
            for (int mi = 0; mi < 2; mi++)
#pragma unroll
                for (int nj = 0; nj < 8; nj++)
                    hmma(acc[mi][nj], a[mi], b[nj >> 1] + (nj & 1) * 2);
        }
    };

    // ---- pipeline ----
    issue(0); cp_commit();
    if (NT > 1) issue(1);
    cp_commit();
    cp_wait1();
    __syncthreads();

    for (int kt = 0; kt < NT; kt++) {
        compute(kt % NSTG);
        if (kt + 2 < NT) issue(kt + 2);
        cp_commit();
        cp_wait1();
        __syncthreads();
    }

    // ---- epilogue: direct fp32 stores ----
    float* Cz = C + (size_t)blockIdx.z * M * Ntot;
#pragma unroll
    for (int mi = 0; mi < 2; mi++) {
        const int row = rowBase + wm * 32 + mi * 16 + (lane >> 2);
#pragma unroll
        for (int nj = 0; nj < 8; nj++) {
            const int col = colBase + wn * 64 + nj * 8 + (lane & 3) * 2;
            *(float2*)(Cz + (size_t)row * Ntot + col) =
                make_float2(acc[mi][nj][0], acc[mi][nj][1]);
            *(float2*)(Cz + (size_t)(row + 8) * Ntot + col) =
                make_float2(acc[mi][nj][2], acc[mi][nj][3]);
        }
    }
}

// =================== fp32 tiled GEMM (basal path, small) ====================
#define BM 128
#define BNN 128
#define BKK 16
#define TM 8
#define TN 8

__global__ void __launch_bounds__(256, 2)
sgemm_nt(const float* __restrict__ A, const float* __restrict__ B,
         float* __restrict__ C, int M, int N, int K, int kChunk)
{
    __shared__ float As[BKK][BM];
    __shared__ float Bs[BKK][BNN];

    const int tid    = threadIdx.x;
    const int brow   = blockIdx.y * BM;
    const int bcol   = blockIdx.x * BNN;
    const int kBegin = blockIdx.z * kChunk;
    const int kEnd   = kBegin + kChunk;

    const int tx = tid & 15;
    const int ty = tid >> 4;
    const int lrow = tid >> 2;
    const int lcol = (tid & 3) << 2;

    const float* Ap = A + (size_t)(brow + lrow) * K + lcol;
    const float* Bp = B + (size_t)(bcol + lrow) * K + lcol;

    float acc[TM][TN];
#pragma unroll
    for (int i = 0; i < TM; i++)
#pragma unroll
        for (int j = 0; j < TN; j++) acc[i][j] = 0.f;

    {
        float4 a0 = *(const float4*)(Ap + kBegin);
        float4 a1 = *(const float4*)(Ap + (size_t)64 * K + kBegin);
        float4 b0 = *(const float4*)(Bp + kBegin);
        float4 b1 = *(const float4*)(Bp + (size_t)64 * K + kBegin);
        As[lcol+0][lrow]    = a0.x; As[lcol+1][lrow]    = a0.y;
        As[lcol+2][lrow]    = a0.z; As[lcol+3][lrow]    = a0.w;
        As[lcol+0][lrow+64] = a1.x; As[lcol+1][lrow+64] = a1.y;
        As[lcol+2][lrow+64] = a1.z; As[lcol+3][lrow+64] = a1.w;
        Bs[lcol+0][lrow]    = b0.x; Bs[lcol+1][lrow]    = b0.y;
        Bs[lcol+2][lrow]    = b0.z; Bs[lcol+3][lrow]    = b0.w;
        Bs[lcol+0][lrow+64] = b1.x; Bs[lcol+1][lrow+64] = b1.y;
        Bs[lcol+2][lrow+64] = b1.z; Bs[lcol+3][lrow+64] = b1.w;
    }
    __syncthreads();

    int k0 = kBegin;
    for (;;) {
        const int kn = k0 + BKK;
        const bool more = kn < kEnd;
        float4 na0, na1, nb0, nb1;
        if (more) {
            na0 = *(const float4*)(Ap + kn);
            na1 = *(const float4*)(Ap + (size_t)64 * K + kn);
            nb0 = *(const float4*)(Bp + kn);
            nb1 = *(const float4*)(Bp + (size_t)64 * K + kn);
        }
#pragma unroll
        for (int kk = 0; kk < BKK; kk++) {
            float af[TM], bf[TN];
#pragma unroll
            for (int i = 0; i < TM; i++) af[i] = As[kk][ty * TM + i];
#pragma unroll
            for (int j = 0; j < TN; j++) bf[j] = Bs[kk][tx * TN + j];
#pragma unroll
            for (int i = 0; i < TM; i++)
#pragma unroll
                for (int j = 0; j < TN; j++) acc[i][j] += af[i] * bf[j];
        }
        if (!more) break;
        __syncthreads();
        As[lcol+0][lrow]    = na0.x; As[lcol+1][lrow]    = na0.y;
        As[lcol+2][lrow]    = na0.z; As[lcol+3][lrow]    = na0.w;
        As[lcol+0][lrow+64] = na1.x; As[lcol+1][lrow+64] = na1.y;
        As[lcol+2][lrow+64] = na1.z; As[lcol+3][lrow+64] = na1.w;
        Bs[lcol+0][lrow]    = nb0.x; Bs[lcol+1][lrow]    = nb0.y;
        Bs[lcol+2][lrow]    = nb0.z; Bs[lcol+3][lrow]    = nb0.w;
        Bs[lcol+0][lrow+64] = nb1.x; Bs[lcol+1][lrow+64] = nb1.y;
        Bs[lcol+2][lrow+64] = nb1.z; Bs[lcol+3][lrow+64] = nb1.w;
        __syncthreads();
        k0 = kn;
    }

    float* Cb = C + (size_t)blockIdx.z * M * N;
#pragma unroll
    for (int i = 0; i < TM; i++) {
        float* Cr = Cb + (size_t)(brow + ty * TM + i) * N + (bcol + tx * TN);
        *(float4*)(Cr)     = make_float4(acc[i][0], acc[i][1], acc[i][2], acc[i][3]);
        *(float4*)(Cr + 4) = make_float4(acc[i][4], acc[i][5], acc[i][6], acc[i][7]);
    }
}

// =========================== small kernels ==================================
__global__ void split_bf16(const float* __restrict__ x,
                           __nv_bfloat16* __restrict__ hi,
                           __nv_bfloat16* __restrict__ lo, int n4)
{
    const int i = blockIdx.x * blockDim.x + threadIdx.x;
    if (i >= n4) return;
    float4 v = ((const float4*)x)[i];
    __nv_bfloat16 h0 = __float2bfloat16(v.x), h1 = __float2bfloat16(v.y);
    __nv_bfloat16 h2 = __float2bfloat16(v.z), h3 = __float2bfloat16(v.w);
    __nv_bfloat16 l0 = __float2bfloat16(v.x - __bfloat162float(h0));
    __nv_bfloat16 l1 = __float2bfloat16(v.y - __bfloat162float(h1));
    __nv_bfloat16 l2 = __float2bfloat16(v.z - __bfloat162float(h2));
    __nv_bfloat16 l3 = __float2bfloat16(v.w - __bfloat162float(h3));
    ((__nv_bfloat162*)hi)[2 * i]     = __halves2bfloat162(h0, h1);
    ((__nv_bfloat162*)hi)[2 * i + 1] = __halves2bfloat162(h2, h3);
    ((__nv_bfloat162*)lo)[2 * i]     = __halves2bfloat162(l0, l1);
    ((__nv_bfloat162*)lo)[2 * i + 1] = __halves2bfloat162(l2, l3);
}

__global__ void init_state()
{
    const int i = blockIdx.x * blockDim.x + threadIdx.x;
    if (i < NBS * NF) { g_ma[i] = 0.f; g_ms[i] = 0.f; g_ml[i] = 0.f; }
    if (i < NB * NF)  g_mb[i] = 0.f;
    if (i < NBS * NL) g_acc[i] = 0.f;
}

__global__ void reduce_basal()
{
    const int i = blockIdx.x * blockDim.x + threadIdx.x;
    if (i >= TSTEPS * NB * NF) return;
    float s = 0.f;
#pragma unroll
    for (int p = 0; p < KSB; p++) s += g_bpart[(size_t)p * (TSTEPS * NB * NF) + i];
    g_basal[i] = s;
}

__global__ void mb_update(int t)
{
    const int i = blockIdx.x * blockDim.x + threadIdx.x;
    if (i < NB * NF) {
        float v = g_mb[i];
        g_mb[i] = v + (g_basal[t * NB * NF + i] - v) * 0.5f;
    }
}

__global__ void mc_spike(int t)
{
    const int i = blockIdx.x * blockDim.x + threadIdx.x;   // over NBS*NF/4
    if (i >= NBS * NF / 4) return;
    const int e = i * 4;
    const int f = e & (NF - 1);
    const int b = e >> 14;
    float4 ap  = ((const float4*)(g_apical + (size_t)t * NBS * NF))[i];
    float4 mav = ((const float4*)g_ma)[i];
    float4 msv = ((const float4*)g_ms)[i];
    float4 mbv = *(const float4*)(g_mb + b * NF + f);
    float4 spv;

    mav.x += (ap.x - mav.x) * 0.5f;
    msv.x += (mav.x + mbv.x - msv.x) * 0.5f;
    spv.x = (msv.x > 1.0f) ? 1.f : 0.f;  msv.x *= (1.f - spv.x);

    mav.y += (ap.y - mav.y) * 0.5f;
    msv.y += (mav.y + mbv.y - msv.y) * 0.5f;
    spv.y = (msv.y > 1.0f) ? 1.f : 0.f;  msv.y *= (1.f - spv.y);

    mav.z += (ap.z - mav.z) * 0.5f;
    msv.z += (mav.z + mbv.z - msv.z) * 0.5f;
    spv.z = (msv.z > 1.0f) ? 1.f : 0.f;  msv.z *= (1.f - spv.z);

    mav.w += (ap.w - mav.w) * 0.5f;
    msv.w += (mav.w + mbv.w - msv.w) * 0.5f;
    spv.w = (msv.w > 1.0f) ? 1.f : 0.f;  msv.w *= (1.f - spv.w);

    ((float4*)g_ma)[i] = mav;
    ((float4*)g_ms)[i] = msv;
    __nv_bfloat162* sp = (__nv_bfloat162*)(g_sp16 + e);
    sp[0] = __halves2bfloat162(__float2bfloat16(spv.x), __float2bfloat16(spv.y));
    sp[1] = __halves2bfloat162(__float2bfloat16(spv.z), __float2bfloat16(spv.w));
}

__global__ void lif_out(const float* __restrict__ b1, const float* __restrict__ W2)
{
    const int gw   = (blockIdx.x * blockDim.x + threadIdx.x) >> 5;
    const int lane = threadIdx.x & 31;
    if (gw >= NBS) return;
    float a[NL];
#pragma unroll
    for (int l = 0; l < NL; l++) a[l] = 0.f;
    const size_t base = (size_t)gw * NH;
#pragma unroll 4
    for (int j = 0; j < NH / 32; j++) {
        const int k = j * 32 + lane;
        const size_t idx = base + k;
        float h = b1[k] + g_hpart[idx] + g_hpart[(size_t)NBS * NH + idx];
        float m = g_ml[idx];
        m += (h - m) * 0.5f;
        const float s = (m > 0.5f) ? 1.f : 0.f;
        g_ml[idx] = m * (1.f - s);
        if (s != 0.f) {
#pragma unroll
            for (int l = 0; l < NL; l++) a[l] += W2[l * NH + k];
        }
    }
#pragma unroll
    for (int l = 0; l < NL; l++) {
#pragma unroll
        for (int o = 16; o; o >>= 1) a[l] += __shfl_xor_sync(0xffffffffu, a[l], o);
    }
    if (lane == 0) {
#pragma unroll
        for (int l = 0; l < NL; l++) g_acc[gw * NL + l] += a[l];
    }
}

__global__ void finalize(const float* __restrict__ b2, float* __restrict__ out)
{
    const int i = blockIdx.x * blockDim.x + threadIdx.x;
    if (i >= NB * NL * NS) return;
    const int s = i % NS;
    const int l = (i / NS) % NL;
    const int b = i / (NS * NL);
    out[i] = g_acc[(b * NS + s) * NL + l] * (1.f / TSTEPS) + b2[l];
}

// ---------------------------------------------------------------------------
extern "C" void kernel_launch(void* const* d_in, const int* in_sizes, int n_in,
                              void* d_out, int out_size)
{
    (void)in_sizes; (void)n_in; (void)out_size;
    const float* se = (const float*)d_in[0];
    const float* te = (const float*)d_in[1];
    const float* Wb = (const float*)d_in[2];
    const float* Wa = (const float*)d_in[3];
    const float* W1 = (const float*)d_in[4];
    const float* b1 = (const float*)d_in[5];
    const float* W2 = (const float*)d_in[6];
    const float* b2 = (const float*)d_in[7];
    float* out = (float*)d_out;

    float *apical, *bpart, *hpart;
    __nv_bfloat16 *teh, *tel, *Wah, *Wal, *W1h, *W1l, *sp16;
    cudaGetSymbolAddress((void**)&apical, g_apical);
    cudaGetSymbolAddress((void**)&bpart,  g_bpart);
    cudaGetSymbolAddress((void**)&hpart,  g_hpart);
    cudaGetSymbolAddress((void**)&teh,    g_teh);
    cudaGetSymbolAddress((void**)&tel,    g_tel);
    cudaGetSymbolAddress((void**)&Wah,    g_Wah);
    cudaGetSymbolAddress((void**)&Wal,    g_Wal);
    cudaGetSymbolAddress((void**)&W1h,    g_W1h);
    cudaGetSymbolAddress((void**)&W1l,    g_W1l);
    cudaGetSymbolAddress((void**)&sp16,   g_sp16);

    // bf16 hi/lo splits
    split_bf16<<<(TSTEPS * NBS * NK / 4 + 255) / 256, 256>>>(te, teh, tel, TSTEPS * NBS * NK / 4);
    split_bf16<<<(NF * NK / 4 + 255) / 256, 256>>>(Wa, Wah, Wal, NF * NK / 4);
    split_bf16<<<(NH * NF / 4 + 255) / 256, 256>>>(W1, W1h, W1l, NH * NF / 4);

    init_state<<<(NBS * NF + 255) / 256, 256>>>();

    // basal (small, fp32 split-K path)
    sgemm_nt<<<dim3(NF / BNN, (TSTEPS * NB) / BM, KSB), 256>>>(
        se, Wb, bpart, TSTEPS * NB, NF, NK, KCH_B);
    reduce_basal<<<(TSTEPS * NB * NF + 255) / 256, 256>>>();

    // apical: 3-pass bf16-split HMMA GEMM, M=16384 N=512 K=3136
    hmma_gemm<<<dim3(NF / 128, (TSTEPS * NBS) / 128, 1), 256>>>(
        teh, Wah, teh, Wal, tel, Wah, 3, NK, NK, NF, apical, TSTEPS * NBS);

    for (int t = 0; t < TSTEPS; t++) {
        mb_update<<<(NB * NF + 255) / 256, 256>>>(t);
        mc_spike<<<(NBS * NF / 4 + 255) / 256, 256>>>(t);
        // h = sp @ W1^T : 2-pass (sp exact in bf16), split-K=2
        hmma_gemm<<<dim3(NH / 128, NBS / 128, KSH), 256>>>(
            sp16, W1h, sp16, W1l, sp16, W1h, 2, NF / KSH, NF, NH, hpart, NBS);
        lif_out<<<(NBS * 32 + 255) / 256, 256>>>(b1, W2);
    }

    finalize<<<(NB * NL * NS + 255) / 256, 256>>>(b2, out);
}

// round 4
// speedup vs baseline: 2.6730x; 1.7091x over previous
#include <cuda_runtime.h>
#include <cuda_bf16.h>
#include <cstdint>

// Problem constants
#define TSTEPS 8
#define NB 64
#define NS 32
#define NBS 2048          // B*S
#define NK 3136           // DS == DT
#define NF 512
#define NH 512
#define NL 18
#define KSB 7             // split-K for basal GEMM
#define KCH_B 448         // 3136 / 7 (multiple of 32)
#define KSH 2             // split-K for h GEMM
#define KCH_H 256         // 512 / 2

// ---------------- scratch (__device__ globals; no allocation allowed) -------
__device__ float g_apical[TSTEPS * NBS * NF];        // 33.5 MB
__device__ float g_bpart[KSB * TSTEPS * NB * NF];    // 7.3 MB
__device__ float g_basal[TSTEPS * NB * NF];
__device__ float g_mball[TSTEPS * NB * NF];          // precomputed mb(t)
__device__ float g_ma[NBS * NF];
__device__ float g_ms[NBS * NF];
__device__ __align__(16) __nv_bfloat16 g_sp16[NBS * NF];   // spikes (exact bf16)
__device__ float g_hpart[KSH * NBS * NH];
__device__ float g_ml[NBS * NH];
__device__ float g_acc[NBS * NL];
// bf16 hi/lo splits
__device__ __align__(16) __nv_bfloat16 g_teh[TSTEPS * NBS * NK];
__device__ __align__(16) __nv_bfloat16 g_tel[TSTEPS * NBS * NK];
__device__ __align__(16) __nv_bfloat16 g_Wah[NF * NK];
__device__ __align__(16) __nv_bfloat16 g_Wal[NF * NK];
__device__ __align__(16) __nv_bfloat16 g_seh[TSTEPS * NB * NK];
__device__ __align__(16) __nv_bfloat16 g_sel[TSTEPS * NB * NK];
__device__ __align__(16) __nv_bfloat16 g_Wbh[NF * NK];
__device__ __align__(16) __nv_bfloat16 g_Wbl[NF * NK];
__device__ __align__(16) __nv_bfloat16 g_W1h[NH * NF];
__device__ __align__(16) __nv_bfloat16 g_W1l[NH * NF];

// ============================ PTX helpers ==================================
__device__ __forceinline__ uint32_t s2u(const void* p) {
    uint32_t a;
    asm("{ .reg .u64 t; cvta.to.shared.u64 t, %1; cvt.u32.u64 %0, t; }"
        : "=r"(a) : "l"(p));
    return a;
}
__device__ __forceinline__ void cp16(uint32_t s, const void* g) {
    asm volatile("cp.async.cg.shared.global [%0], [%1], 16;" :: "r"(s), "l"(g) : "memory");
}
__device__ __forceinline__ void cp_commit() {
    asm volatile("cp.async.commit_group;" ::: "memory");
}
__device__ __forceinline__ void cp_wait1() {
    asm volatile("cp.async.wait_group 1;" ::: "memory");
}
__device__ __forceinline__ void ldmx4(uint32_t* r, uint32_t a) {
    asm volatile("ldmatrix.sync.aligned.m8n8.x4.shared.b16 {%0,%1,%2,%3}, [%4];"
                 : "=r"(r[0]), "=r"(r[1]), "=r"(r[2]), "=r"(r[3]) : "r"(a));
}
__device__ __forceinline__ void hmma(float* c, const uint32_t* a, const uint32_t* b) {
    asm volatile(
        "mma.sync.aligned.m16n8k16.row.col.f32.bf16.bf16.f32 "
        "{%0,%1,%2,%3}, {%4,%5,%6,%7}, {%8,%9}, {%0,%1,%2,%3};"
        : "+f"(c[0]), "+f"(c[1]), "+f"(c[2]), "+f"(c[3])
        : "r"(a[0]), "r"(a[1]), "r"(a[2]), "r"(a[3]), "r"(b[0]), "r"(b[1]));
}

// ================= fused bf16-split HMMA GEMM ===============================
// Computes C = Ah*Bh^T + Ah*Bl^T (+ Al*Bh^T if MODE==3), all K-major,
// single K sweep: each k-tile loads Ah/(Al)/Bh/Bl once, issues all products
// into one fp32 accumulator. CTA tile 128x128, BK=32, 256 threads
// (8 warps: 4 M x 2 N; warp tile 32x64), 3-stage cp.async pipeline.
// blockIdx.z = K split; partial to C + z*M*Ntot (fixed-order reduce later).
#define BKT 32
#define NSTG 3

template<int MODE>
__global__ void __launch_bounds__(256, 2)
hmma_fused(const __nv_bfloat16* __restrict__ Ah, const __nv_bfloat16* __restrict__ Al,
           const __nv_bfloat16* __restrict__ Bh, const __nv_bfloat16* __restrict__ Bl,
           int kChunk, int lda, int Ntot, float* __restrict__ C, int M)
{
    extern __shared__ __nv_bfloat16 dsm[];
    constexpr int TILE   = 128 * BKT;                      // elements per tile
    constexpr int NTILES = (MODE == 3) ? 4 : 3;            // Ah,(Al),Bh,Bl
    constexpr int STG    = NTILES * TILE;                  // elems per stage
    constexpr int OFF_AL = TILE;
    constexpr int OFF_BH = (MODE == 3) ? 2 * TILE : TILE;
    constexpr int OFF_BL = OFF_BH + TILE;

    const int tid  = threadIdx.x;
    const int wid  = tid >> 5;
    const int lane = tid & 31;
    const int wm   = wid & 3;
    const int wn   = wid >> 2;

    const int rowBase = blockIdx.y * 128;
    const int colBase = blockIdx.x * 128;
    const int kOff    = blockIdx.z * kChunk;
    const int NT      = kChunk / BKT;

    const uint32_t smemB = s2u(dsm);

    float acc[2][8][4];
#pragma unroll
    for (int mi = 0; mi < 2; mi++)
#pragma unroll
        for (int nj = 0; nj < 8; nj++)
#pragma unroll
            for (int q = 0; q < 4; q++) acc[mi][nj][q] = 0.f;

    // ---- stage fill: each thread does NTILES*2 cp.async(16B) ----
    auto issue = [&](int kt) {
        const int s  = kt % NSTG;
        const int kl = kt * BKT + kOff;
        const uint32_t base = smemB + (uint32_t)(s * STG) * 2;
#pragma unroll
        for (int i = 0; i < 2; i++) {
            const int v = tid + i * 256;                 // 0..511
            const int m = v >> 2, u = v & 3;
            const uint32_t so = (uint32_t)(m * 64 + ((u ^ ((m >> 1) & 3)) << 4));
            const size_t ga = (size_t)(rowBase + m) * lda + kl + u * 8;
            const size_t gb = (size_t)(colBase + m) * lda + kl + u * 8;
            cp16(base + so, Ah + ga);
            if (MODE == 3) cp16(base + OFF_AL * 2 + so, Al + ga);
            cp16(base + OFF_BH * 2 + so, Bh + gb);
            cp16(base + OFF_BL * 2 + so, Bl + gb);
        }
    };

    // ---- compute one BK=32 stage: all products ----
    auto compute = [&](int s) {
        const uint32_t base = smemB + (uint32_t)(s * STG) * 2;
#pragma unroll
        for (int k16 = 0; k16 < 2; k16++) {
            uint32_t ah[2][4], al[2][4];
#pragma unroll
            for (int mi = 0; mi < 2; mi++) {
                const int row = wm * 32 + mi * 16 + (lane & 15);
                const int u   = k16 * 2 + (lane >> 4);
                const uint32_t off = (uint32_t)(row * 64 + ((u ^ ((row >> 1) & 3)) << 4));
                ldmx4(ah[mi], base + off);
                if (MODE == 3) ldmx4(al[mi], base + OFF_AL * 2 + off);
            }
#pragma unroll
            for (int np = 0; np < 4; np++) {
                const int n = wn * 64 + np * 16 + ((lane >> 4) << 3) + (lane & 7);
                const int u = k16 * 2 + ((lane >> 3) & 1);
                const uint32_t boff = (uint32_t)(n * 64 + ((u ^ ((n >> 1) & 3)) << 4));
                uint32_t bh[4], bl[4];
                ldmx4(bh, base + OFF_BH * 2 + boff);
                ldmx4(bl, base + OFF_BL * 2 + boff);
#pragma unroll
                for (int mi = 0; mi < 2; mi++) {
                    hmma(acc[mi][2 * np],     ah[mi], bh);
                    hmma(acc[mi][2 * np + 1], ah[mi], bh + 2);
                    hmma(acc[mi][2 * np],     ah[mi], bl);
                    hmma(acc[mi][2 * np + 1], ah[mi], bl + 2);
                    if (MODE == 3) {
                        hmma(acc[mi][2 * np],     al[mi], bh);
                        hmma(acc[mi][2 * np + 1], al[mi], bh + 2);
                    }
                }
            }
        }
    };

    // ---- pipeline ----
    issue(0); cp_commit();
    if (NT > 1) issue(1);
    cp_commit();
    cp_wait1();
    __syncthreads();

    for (int kt = 0; kt < NT; kt++) {
        compute(kt % NSTG);
        if (kt + 2 < NT) issue(kt + 2);
        cp_commit();
        cp_wait1();
        __syncthreads();
    }

    // ---- epilogue ----
    float* Cz = C + (size_t)blockIdx.z * M * Ntot;
#pragma unroll
    for (int mi = 0; mi < 2; mi++) {
        const int row = rowBase + wm * 32 + mi * 16 + (lane >> 2);
#pragma unroll
        for (int nj = 0; nj < 8; nj++) {
            const int col = colBase + wn * 64 + nj * 8 + (lane & 3) * 2;
            *(float2*)(Cz + (size_t)row * Ntot + col) =
                make_float2(acc[mi][nj][0], acc[mi][nj][1]);
            *(float2*)(Cz + (size_t)(row + 8) * Ntot + col) =
                make_float2(acc[mi][nj][2], acc[mi][nj][3]);
        }
    }
}

// =========================== small kernels ==================================
__global__ void split_bf16(const float* __restrict__ x,
                           __nv_bfloat16* __restrict__ hi,
                           __nv_bfloat16* __restrict__ lo, int n4)
{
    const int i = blockIdx.x * blockDim.x + threadIdx.x;
    if (i >= n4) return;
    float4 v = ((const float4*)x)[i];
    __nv_bfloat16 h0 = __float2bfloat16(v.x), h1 = __float2bfloat16(v.y);
    __nv_bfloat16 h2 = __float2bfloat16(v.z), h3 = __float2bfloat16(v.w);
    __nv_bfloat16 l0 = __float2bfloat16(v.x - __bfloat162float(h0));
    __nv_bfloat16 l1 = __float2bfloat16(v.y - __bfloat162float(h1));
    __nv_bfloat16 l2 = __float2bfloat16(v.z - __bfloat162float(h2));
    __nv_bfloat16 l3 = __float2bfloat16(v.w - __bfloat162float(h3));
    ((__nv_bfloat162*)hi)[2 * i]     = __halves2bfloat162(h0, h1);
    ((__nv_bfloat162*)hi)[2 * i + 1] = __halves2bfloat162(h2, h3);
    ((__nv_bfloat162*)lo)[2 * i]     = __halves2bfloat162(l0, l1);
    ((__nv_bfloat162*)lo)[2 * i + 1] = __halves2bfloat162(l2, l3);
}

__global__ void init_state()
{
    const int i = blockIdx.x * blockDim.x + threadIdx.x;
    if (i < NBS * NF) { g_ma[i] = 0.f; g_ms[i] = 0.f; g_ml[i] = 0.f; }
    if (i < NBS * NL) g_acc[i] = 0.f;
}

// reduce basal split-K partials + precompute mb(t) recurrence in one pass
__global__ void reduce_basal_mb()
{
    const int i = blockIdx.x * blockDim.x + threadIdx.x;   // over NB*NF
    if (i >= NB * NF) return;
    float mb = 0.f;
#pragma unroll
    for (int t = 0; t < TSTEPS; t++) {
        const int e = t * NB * NF + i;
        float s = 0.f;
#pragma unroll
        for (int p = 0; p < KSB; p++) s += g_bpart[(size_t)p * (TSTEPS * NB * NF) + e];
        mb += (s - mb) * 0.5f;
        g_mball[e] = mb;
    }
}

__global__ void mc_spike(int t)
{
    const int i = blockIdx.x * blockDim.x + threadIdx.x;   // over NBS*NF/4
    if (i >= NBS * NF / 4) return;
    const int e = i * 4;
    const int f = e & (NF - 1);
    const int b = e >> 14;
    float4 ap  = ((const float4*)(g_apical + (size_t)t * NBS * NF))[i];
    float4 mav = ((const float4*)g_ma)[i];
    float4 msv = ((const float4*)g_ms)[i];
    float4 mbv = *(const float4*)(g_mball + t * NB * NF + b * NF + f);
    float4 spv;

    mav.x += (ap.x - mav.x) * 0.5f;
    msv.x += (mav.x + mbv.x - msv.x) * 0.5f;
    spv.x = (msv.x > 1.0f) ? 1.f : 0.f;  msv.x *= (1.f - spv.x);

    mav.y += (ap.y - mav.y) * 0.5f;
    msv.y += (mav.y + mbv.y - msv.y) * 0.5f;
    spv.y = (msv.y > 1.0f) ? 1.f : 0.f;  msv.y *= (1.f - spv.y);

    mav.z += (ap.z - mav.z) * 0.5f;
    msv.z += (mav.z + mbv.z - msv.z) * 0.5f;
    spv.z = (msv.z > 1.0f) ? 1.f : 0.f;  msv.z *= (1.f - spv.z);

    mav.w += (ap.w - mav.w) * 0.5f;
    msv.w += (mav.w + mbv.w - msv.w) * 0.5f;
    spv.w = (msv.w > 1.0f) ? 1.f : 0.f;  msv.w *= (1.f - spv.w);

    ((float4*)g_ma)[i] = mav;
    ((float4*)g_ms)[i] = msv;
    __nv_bfloat162* sp = (__nv_bfloat162*)(g_sp16 + e);
    sp[0] = __halves2bfloat162(__float2bfloat16(spv.x), __float2bfloat16(spv.y));
    sp[1] = __halves2bfloat162(__float2bfloat16(spv.z), __float2bfloat16(spv.w));
}

__global__ void lif_out(const float* __restrict__ b1, const float* __restrict__ W2)
{
    const int gw   = (blockIdx.x * blockDim.x + threadIdx.x) >> 5;
    const int lane = threadIdx.x & 31;
    if (gw >= NBS) return;
    float a[NL];
#pragma unroll
    for (int l = 0; l < NL; l++) a[l] = 0.f;
    const size_t base = (size_t)gw * NH;
#pragma unroll 4
    for (int j = 0; j < NH / 32; j++) {
        const int k = j * 32 + lane;
        const size_t idx = base + k;
        float h = b1[k] + g_hpart[idx] + g_hpart[(size_t)NBS * NH + idx];
        float m = g_ml[idx];
        m += (h - m) * 0.5f;
        const float s = (m > 0.5f) ? 1.f : 0.f;
        g_ml[idx] = m * (1.f - s);
        if (s != 0.f) {
#pragma unroll
            for (int l = 0; l < NL; l++) a[l] += W2[l * NH + k];
        }
    }
#pragma unroll
    for (int l = 0; l < NL; l++) {
#pragma unroll
        for (int o = 16; o; o >>= 1) a[l] += __shfl_xor_sync(0xffffffffu, a[l], o);
    }
    if (lane == 0) {
#pragma unroll
        for (int l = 0; l < NL; l++) g_acc[gw * NL + l] += a[l];
    }
}

__global__ void finalize(const float* __restrict__ b2, float* __restrict__ out)
{
    const int i = blockIdx.x * blockDim.x + threadIdx.x;
    if (i >= NB * NL * NS) return;
    const int s = i % NS;
    const int l = (i / NS) % NL;
    const int b = i / (NS * NL);
    out[i] = g_acc[(b * NS + s) * NL + l] * (1.f / TSTEPS) + b2[l];
}

// ---------------------------------------------------------------------------
extern "C" void kernel_launch(void* const* d_in, const int* in_sizes, int n_in,
                              void* d_out, int out_size)
{
    (void)in_sizes; (void)n_in; (void)out_size;
    const float* se = (const float*)d_in[0];
    const float* te = (const float*)d_in[1];
    const float* Wb = (const float*)d_in[2];
    const float* Wa = (const float*)d_in[3];
    const float* W1 = (const float*)d_in[4];
    const float* b1 = (const float*)d_in[5];
    const float* W2 = (const float*)d_in[6];
    const float* b2 = (const float*)d_in[7];
    float* out = (float*)d_out;

    float *apical, *bpart, *hpart;
    __nv_bfloat16 *teh, *tel, *Wah, *Wal, *seh, *sel, *Wbh, *Wbl, *W1h, *W1l, *sp16;
    cudaGetSymbolAddress((void**)&apical, g_apical);
    cudaGetSymbolAddress((void**)&bpart,  g_bpart);
    cudaGetSymbolAddress((void**)&hpart,  g_hpart);
    cudaGetSymbolAddress((void**)&teh,    g_teh);
    cudaGetSymbolAddress((void**)&tel,    g_tel);
    cudaGetSymbolAddress((void**)&Wah,    g_Wah);
    cudaGetSymbolAddress((void**)&Wal,    g_Wal);
    cudaGetSymbolAddress((void**)&seh,    g_seh);
    cudaGetSymbolAddress((void**)&sel,    g_sel);
    cudaGetSymbolAddress((void**)&Wbh,    g_Wbh);
    cudaGetSymbolAddress((void**)&Wbl,    g_Wbl);
    cudaGetSymbolAddress((void**)&W1h,    g_W1h);
    cudaGetSymbolAddress((void**)&W1l,    g_W1l);
    cudaGetSymbolAddress((void**)&sp16,   g_sp16);

    const int SMEM3 = 4 * 128 * BKT * 2 * NSTG;   // 98304
    const int SMEM2 = 3 * 128 * BKT * 2 * NSTG;   // 73728
    cudaFuncSetAttribute(hmma_fused<3>, cudaFuncAttributeMaxDynamicSharedMemorySize, SMEM3);
    cudaFuncSetAttribute(hmma_fused<2>, cudaFuncAttributeMaxDynamicSharedMemorySize, SMEM2);

    // bf16 hi/lo splits
    split_bf16<<<(TSTEPS * NBS * NK / 4 + 255) / 256, 256>>>(te, teh, tel, TSTEPS * NBS * NK / 4);
    split_bf16<<<(NF * NK / 4 + 255) / 256, 256>>>(Wa, Wah, Wal, NF * NK / 4);
    split_bf16<<<(TSTEPS * NB * NK / 4 + 255) / 256, 256>>>(se, seh, sel, TSTEPS * NB * NK / 4);
    split_bf16<<<(NF * NK / 4 + 255) / 256, 256>>>(Wb, Wbh, Wbl, NF * NK / 4);
    split_bf16<<<(NH * NF / 4 + 255) / 256, 256>>>(W1, W1h, W1l, NH * NF / 4);

    init_state<<<(NBS * NF + 255) / 256, 256>>>();

    // basal: fused-split HMMA, M=512 K=3136 N=512, split-K=7
    hmma_fused<3><<<dim3(NF / 128, (TSTEPS * NB) / 128, KSB), 256, SMEM3>>>(
        seh, sel, Wbh, Wbl, KCH_B, NK, NF, bpart, TSTEPS * NB);
    reduce_basal_mb<<<(NB * NF + 255) / 256, 256>>>();

    // apical: fused-split HMMA, M=16384 N=512 K=3136, single K sweep
    hmma_fused<3><<<dim3(NF / 128, (TSTEPS * NBS) / 128, 1), 256, SMEM3>>>(
        teh, tel, Wah, Wal, NK, NK, NF, apical, TSTEPS * NBS);

    for (int t = 0; t < TSTEPS; t++) {
        mc_spike<<<(NBS * NF / 4 + 255) / 256, 256>>>(t);
        // h = sp @ W1^T : sp exact bf16, W1 split => 2 products, split-K=2
        hmma_fused<2><<<dim3(NH / 128, NBS / 128, KSH), 256, SMEM2>>>(
            sp16, sp16, W1h, W1l, KCH_H, NF, NH, hpart, NBS);
        lif_out<<<(NBS * 32 + 255) / 256, 256>>>(b1, W2);
    }

    finalize<<<(NB * NL * NS + 255) / 256, 256>>>(b2, out);
}

// round 5
// speedup vs baseline: 2.7380x; 1.0243x over previous
#include <cuda_runtime.h>
#include <cuda_bf16.h>
#include <cstdint>

// Problem constants
#define TSTEPS 8
#define NB 64
#define NS 32
#define NBS 2048          // B*S
#define NK 3136           // DS == DT
#define NF 512
#define NH 512
#define NL 18
#define KSB 7             // split-K for basal GEMM
#define KCH_B 448         // 3136 / 7 (multiple of 32)
#define KSH 2             // split-K for h GEMM
#define KCH_H 256         // 512 / 2

// ---------------- scratch (__device__ globals; no allocation allowed) -------
__device__ float g_apical[TSTEPS * NBS * NF];        // 33.5 MB
__device__ float g_bpart[KSB * TSTEPS * NB * NF];
__device__ float g_mball[TSTEPS * NB * NF];          // precomputed mb(t)
__device__ float g_ma[NBS * NF];
__device__ float g_ms[NBS * NF];
__device__ __align__(16) __nv_bfloat16 g_sp16[NBS * NF];   // spikes (exact bf16)
__device__ float g_hpart[KSH * NBS * NH];
__device__ float g_ml[NBS * NH];
__device__ float g_acc[NBS * NL];
// bf16 hi/lo splits (weights only)
__device__ __align__(16) __nv_bfloat16 g_Wah[NF * NK];
__device__ __align__(16) __nv_bfloat16 g_Wal[NF * NK];
__device__ __align__(16) __nv_bfloat16 g_Wbh[NF * NK];
__device__ __align__(16) __nv_bfloat16 g_Wbl[NF * NK];
__device__ __align__(16) __nv_bfloat16 g_W1h[NH * NF];
__device__ __align__(16) __nv_bfloat16 g_W1l[NH * NF];

// ============================ PTX helpers ==================================
__device__ __forceinline__ uint32_t s2u(const void* p) {
    uint32_t a;
    asm("{ .reg .u64 t; cvta.to.shared.u64 t, %1; cvt.u32.u64 %0, t; }"
        : "=r"(a) : "l"(p));
    return a;
}
__device__ __forceinline__ void cp16(uint32_t s, const void* g) {
    asm volatile("cp.async.cg.shared.global [%0], [%1], 16;" :: "r"(s), "l"(g) : "memory");
}
__device__ __forceinline__ void cp_commit() {
    asm volatile("cp.async.commit_group;" ::: "memory");
}
__device__ __forceinline__ void cp_wait1() {
    asm volatile("cp.async.wait_group 1;" ::: "memory");
}
__device__ __forceinline__ void ldmx4(uint32_t* r, uint32_t a) {
    asm volatile("ldmatrix.sync.aligned.m8n8.x4.shared.b16 {%0,%1,%2,%3}, [%4];"
                 : "=r"(r[0]), "=r"(r[1]), "=r"(r[2]), "=r"(r[3]) : "r"(a));
}
__device__ __forceinline__ void hmma(float* c, const uint32_t* a, const uint32_t* b) {
    asm volatile(
        "mma.sync.aligned.m16n8k16.row.col.f32.bf16.bf16.f32 "
        "{%0,%1,%2,%3}, {%4,%5,%6,%7}, {%8,%9}, {%0,%1,%2,%3};"
        : "+f"(c[0]), "+f"(c[1]), "+f"(c[2]), "+f"(c[3])
        : "r"(a[0]), "r"(a[1]), "r"(a[2]), "r"(a[3]), "r"(b[0]), "r"(b[1]));
}

// split 4 fp32 -> packed bf16x2 hi pair + lo pair (RN split, same as split_bf16)
__device__ __forceinline__ void split4(float4 f, uint2& hi, uint2& lo) {
    __nv_bfloat16 h0 = __float2bfloat16(f.x), h1 = __float2bfloat16(f.y);
    __nv_bfloat16 h2 = __float2bfloat16(f.z), h3 = __float2bfloat16(f.w);
    __nv_bfloat162 H01 = __halves2bfloat162(h0, h1);
    __nv_bfloat162 H23 = __halves2bfloat162(h2, h3);
    __nv_bfloat162 L01 = __halves2bfloat162(
        __float2bfloat16(f.x - __bfloat162float(h0)),
        __float2bfloat16(f.y - __bfloat162float(h1)));
    __nv_bfloat162 L23 = __halves2bfloat162(
        __float2bfloat16(f.z - __bfloat162float(h2)),
        __float2bfloat16(f.w - __bfloat162float(h3)));
    hi.x = *(uint32_t*)&H01; hi.y = *(uint32_t*)&H23;
    lo.x = *(uint32_t*)&L01; lo.y = *(uint32_t*)&L23;
}

// ================= fused bf16-split HMMA GEMM ===============================
// MODE==3: A is fp32 in gmem; producer LDGs fp32, splits to (Ah, Al) bf16 in
//          smem in-kernel; computes C = Ah*Bh^T + Ah*Bl^T + Al*Bh^T.
// MODE==2: A is exact bf16 in gmem (spikes); C = A*Bh^T + A*Bl^T.
// B always pre-split bf16 (weights, small), loaded via cp.async.
// CTA tile 128x128, BK=32, 256 threads (8 warps: 4Mx2N, warp tile 32x64),
// 3-stage pipeline. blockIdx.z = K split; partial to C + z*M*Ntot.
#define BKT 32
#define NSTG 3

template<int MODE>
__global__ void __launch_bounds__(256, 2)
hmma_fused(const void* __restrict__ Araw,
           const __nv_bfloat16* __restrict__ Bh, const __nv_bfloat16* __restrict__ Bl,
           int kChunk, int lda, int Ntot, float* __restrict__ C, int M)
{
    extern __shared__ __nv_bfloat16 dsm[];
    constexpr int TILE   = 128 * BKT;                      // elements per tile
    constexpr int NTILES = (MODE == 3) ? 4 : 3;            // Ah,(Al),Bh,Bl
    constexpr int STG    = NTILES * TILE;
    constexpr int OFF_AL = TILE;
    constexpr int OFF_BH = (MODE == 3) ? 2 * TILE : TILE;
    constexpr int OFF_BL = OFF_BH + TILE;

    const int tid  = threadIdx.x;
    const int wid  = tid >> 5;
    const int lane = tid & 31;
    const int wm   = wid & 3;
    const int wn   = wid >> 2;

    const int rowBase = blockIdx.y * 128;
    const int colBase = blockIdx.x * 128;
    const int kOff    = blockIdx.z * kChunk;
    const int NT      = kChunk / BKT;

    const uint32_t smemB = s2u(dsm);
    const float* A32        = (const float*)Araw;
    const __nv_bfloat16* A16 = (const __nv_bfloat16*)Araw;

    float acc[2][8][4];
#pragma unroll
    for (int mi = 0; mi < 2; mi++)
#pragma unroll
        for (int nj = 0; nj < 8; nj++)
#pragma unroll
            for (int q = 0; q < 4; q++) acc[mi][nj][q] = 0.f;

    // ---- B producer (cp.async, bf16 hi+lo) ----
    auto issueB = [&](int kt) {
        const int s  = kt % NSTG;
        const int kl = kt * BKT + kOff;
        const uint32_t base = smemB + (uint32_t)(s * STG) * 2;
#pragma unroll
        for (int i = 0; i < 2; i++) {
            const int v = tid + i * 256;
            const int m = v >> 2, u = v & 3;
            const uint32_t so = (uint32_t)(m * 64 + ((u ^ ((m >> 1) & 3)) << 4));
            const size_t gb = (size_t)(colBase + m) * lda + kl + u * 8;
            cp16(base + OFF_BH * 2 + so, Bh + gb);
            cp16(base + OFF_BL * 2 + so, Bl + gb);
        }
    };
    // ---- A producer, MODE2: exact bf16 via cp.async ----
    auto issueA2 = [&](int kt) {
        const int s  = kt % NSTG;
        const int kl = kt * BKT + kOff;
        const uint32_t base = smemB + (uint32_t)(s * STG) * 2;
#pragma unroll
        for (int i = 0; i < 2; i++) {
            const int v = tid + i * 256;
            const int m = v >> 2, u = v & 3;
            const uint32_t so = (uint32_t)(m * 64 + ((u ^ ((m >> 1) & 3)) << 4));
            cp16(base + so, A16 + (size_t)(rowBase + m) * lda + kl + u * 8);
        }
    };
    // ---- A producer, MODE3: LDG fp32 into regs ----
    auto ldgA = [&](int kt, float4* f) {
#pragma unroll
        for (int i = 0; i < 4; i++) {
            const int fv = tid + i * 256;                 // 0..1023
            const int row = fv >> 3, u4 = fv & 7;         // 8 float4 per row
            f[i] = *(const float4*)(A32 + (size_t)(rowBase + row) * lda
                                    + kt * BKT + kOff + u4 * 4);
        }
    };
    // ---- split + store A hi/lo tiles ----
    auto stsA = [&](int kt, const float4* f) {
        const int s = kt % NSTG;
        char* base = (char*)dsm + (size_t)(s * STG) * 2;
#pragma unroll
        for (int i = 0; i < 4; i++) {
            const int fv = tid + i * 256;
            const int row = fv >> 3, u4 = fv & 7;
            const int u = u4 >> 1, half = u4 & 1;
            const uint32_t so = (uint32_t)(row * 64 + ((u ^ ((row >> 1) & 3)) << 4) + half * 8);
            uint2 hi, lo;
            split4(f[i], hi, lo);
            *(uint2*)(base + so)              = hi;
            *(uint2*)(base + OFF_AL * 2 + so) = lo;
        }
    };

    // ---- compute one BK=32 stage: all products ----
    auto compute = [&](int s) {
        const uint32_t base = smemB + (uint32_t)(s * STG) * 2;
#pragma unroll
        for (int k16 = 0; k16 < 2; k16++) {
            uint32_t ah[2][4], al[2][4];
#pragma unroll
            for (int mi = 0; mi < 2; mi++) {
                const int row = wm * 32 + mi * 16 + (lane & 15);
                const int u   = k16 * 2 + (lane >> 4);
                const uint32_t off = (uint32_t)(row * 64 + ((u ^ ((row >> 1) & 3)) << 4));
                ldmx4(ah[mi], base + off);
                if (MODE == 3) ldmx4(al[mi], base + OFF_AL * 2 + off);
            }
#pragma unroll
            for (int np = 0; np < 4; np++) {
                const int n = wn * 64 + np * 16 + ((lane >> 4) << 3) + (lane & 7);
                const int u = k16 * 2 + ((lane >> 3) & 1);
                const uint32_t boff = (uint32_t)(n * 64 + ((u ^ ((n >> 1) & 3)) << 4));
                uint32_t bh[4], bl[4];
                ldmx4(bh, base + OFF_BH * 2 + boff);
                ldmx4(bl, base + OFF_BL * 2 + boff);
#pragma unroll
                for (int mi = 0; mi < 2; mi++) {
                    hmma(acc[mi][2 * np],     ah[mi], bh);
                    hmma(acc[mi][2 * np + 1], ah[mi], bh + 2);
                    hmma(acc[mi][2 * np],     ah[mi], bl);
                    hmma(acc[mi][2 * np + 1], ah[mi], bl + 2);
                    if (MODE == 3) {
                        hmma(acc[mi][2 * np],     al[mi], bh);
                        hmma(acc[mi][2 * np + 1], al[mi], bh + 2);
                    }
                }
            }
        }
    };

    // ---- prologue: fill stages 0,1 ----
    float4 f[4];
    if (MODE == 3) { ldgA(0, f); stsA(0, f); } else { issueA2(0); }
    issueB(0); cp_commit();
    if (NT > 1) {
        if (MODE == 3) { ldgA(1, f); stsA(1, f); } else { issueA2(1); }
        issueB(1);
    }
    cp_commit();
    cp_wait1();
    __syncthreads();

    // ---- mainloop ----
    for (int kt = 0; kt < NT; kt++) {
        const bool pf = (kt + 2 < NT);
        if (MODE == 3 && pf) ldgA(kt + 2, f);        // LDG hidden under MMA
        if (pf) { if (MODE == 2) issueA2(kt + 2); issueB(kt + 2); }
        cp_commit();
        compute(kt % NSTG);
        if (MODE == 3 && pf) stsA(kt + 2, f);        // convert + store after MMA
        cp_wait1();
        __syncthreads();
    }

    // ---- epilogue ----
    float* Cz = C + (size_t)blockIdx.z * M * Ntot;
#pragma unroll
    for (int mi = 0; mi < 2; mi++) {
        const int row = rowBase + wm * 32 + mi * 16 + (lane >> 2);
#pragma unroll
        for (int nj = 0; nj < 8; nj++) {
            const int col = colBase + wn * 64 + nj * 8 + (lane & 3) * 2;
            *(float2*)(Cz + (size_t)row * Ntot + col) =
                make_float2(acc[mi][nj][0], acc[mi][nj][1]);
            *(float2*)(Cz + (size_t)(row + 8) * Ntot + col) =
                make_float2(acc[mi][nj][2], acc[mi][nj][3]);
        }
    }
}

// =========================== small kernels ==================================
__global__ void split_bf16(const float* __restrict__ x,
                           __nv_bfloat16* __restrict__ hi,
                           __nv_bfloat16* __restrict__ lo, int n4)
{
    const int i = blockIdx.x * blockDim.x + threadIdx.x;
    if (i >= n4) return;
    float4 v = ((const float4*)x)[i];
    __nv_bfloat16 h0 = __float2bfloat16(v.x), h1 = __float2bfloat16(v.y);
    __nv_bfloat16 h2 = __float2bfloat16(v.z), h3 = __float2bfloat16(v.w);
    __nv_bfloat16 l0 = __float2bfloat16(v.x - __bfloat162float(h0));
    __nv_bfloat16 l1 = __float2bfloat16(v.y - __bfloat162float(h1));
    __nv_bfloat16 l2 = __float2bfloat16(v.z - __bfloat162float(h2));
    __nv_bfloat16 l3 = __float2bfloat16(v.w - __bfloat162float(h3));
    ((__nv_bfloat162*)hi)[2 * i]     = __halves2bfloat162(h0, h1);
    ((__nv_bfloat162*)hi)[2 * i + 1] = __halves2bfloat162(h2, h3);
    ((__nv_bfloat162*)lo)[2 * i]     = __halves2bfloat162(l0, l1);
    ((__nv_bfloat162*)lo)[2 * i + 1] = __halves2bfloat162(l2, l3);
}

__global__ void init_state()
{
    const int i = blockIdx.x * blockDim.x + threadIdx.x;
    if (i < NBS * NF) { g_ma[i] = 0.f; g_ms[i] = 0.f; g_ml[i] = 0.f; }
    if (i < NBS * NL) g_acc[i] = 0.f;
}

// reduce basal split-K partials + precompute mb(t) recurrence in one pass
__global__ void reduce_basal_mb()
{
    const int i = blockIdx.x * blockDim.x + threadIdx.x;   // over NB*NF
    if (i >= NB * NF) return;
    float mb = 0.f;
#pragma unroll
    for (int t = 0; t < TSTEPS; t++) {
        const int e = t * NB * NF + i;
        float s = 0.f;
#pragma unroll
        for (int p = 0; p < KSB; p++) s += g_bpart[(size_t)p * (TSTEPS * NB * NF) + e];
        mb += (s - mb) * 0.5f;
        g_mball[e] = mb;
    }
}

__global__ void mc_spike(int t)
{
    const int i = blockIdx.x * blockDim.x + threadIdx.x;   // over NBS*NF/4
    if (i >= NBS * NF / 4) return;
    const int e = i * 4;
    const int f = e & (NF - 1);
    const int b = e >> 14;
    float4 ap  = ((const float4*)(g_apical + (size_t)t * NBS * NF))[i];
    float4 mav = ((const float4*)g_ma)[i];
    float4 msv = ((const float4*)g_ms)[i];
    float4 mbv = *(const float4*)(g_mball + t * NB * NF + b * NF + f);
    float4 spv;

    mav.x += (ap.x - mav.x) * 0.5f;
    msv.x += (mav.x + mbv.x - msv.x) * 0.5f;
    spv.x = (msv.x > 1.0f) ? 1.f : 0.f;  msv.x *= (1.f - spv.x);

    mav.y += (ap.y - mav.y) * 0.5f;
    msv.y += (mav.y + mbv.y - msv.y) * 0.5f;
    spv.y = (msv.y > 1.0f) ? 1.f : 0.f;  msv.y *= (1.f - spv.y);

    mav.z += (ap.z - mav.z) * 0.5f;
    msv.z += (mav.z + mbv.z - msv.z) * 0.5f;
    spv.z = (msv.z > 1.0f) ? 1.f : 0.f;  msv.z *= (1.f - spv.z);

    mav.w += (ap.w - mav.w) * 0.5f;
    msv.w += (mav.w + mbv.w - msv.w) * 0.5f;
    spv.w = (msv.w > 1.0f) ? 1.f : 0.f;  msv.w *= (1.f - spv.w);

    ((float4*)g_ma)[i] = mav;
    ((float4*)g_ms)[i] = msv;
    __nv_bfloat162* sp = (__nv_bfloat162*)(g_sp16 + e);
    sp[0] = __halves2bfloat162(__float2bfloat16(spv.x), __float2bfloat16(spv.y));
    sp[1] = __halves2bfloat162(__float2bfloat16(spv.z), __float2bfloat16(spv.w));
}

__global__ void lif_out(const float* __restrict__ b1, const float* __restrict__ W2)
{
    const int gw   = (blockIdx.x * blockDim.x + threadIdx.x) >> 5;
    const int lane = threadIdx.x & 31;
    if (gw >= NBS) return;
    float a[NL];
#pragma unroll
    for (int l = 0; l < NL; l++) a[l] = 0.f;
    const size_t base = (size_t)gw * NH;
#pragma unroll 4
    for (int j = 0; j < NH / 32; j++) {
        const int k = j * 32 + lane;
        const size_t idx = base + k;
        float h = b1[k] + g_hpart[idx] + g_hpart[(size_t)NBS * NH + idx];
        float m = g_ml[idx];
        m += (h - m) * 0.5f;
        const float s = (m > 0.5f) ? 1.f : 0.f;
        g_ml[idx] = m * (1.f - s);
        if (s != 0.f) {
#pragma unroll
            for (int l = 0; l < NL; l++) a[l] += W2[l * NH + k];
        }
    }
#pragma unroll
    for (int l = 0; l < NL; l++) {
#pragma unroll
        for (int o = 16; o; o >>= 1) a[l] += __shfl_xor_sync(0xffffffffu, a[l], o);
    }
    if (lane == 0) {
#pragma unroll
        for (int l = 0; l < NL; l++) g_acc[gw * NL + l] += a[l];
    }
}

__global__ void finalize(const float* __restrict__ b2, float* __restrict__ out)
{
    const int i = blockIdx.x * blockDim.x + threadIdx.x;
    if (i >= NB * NL * NS) return;
    const int s = i % NS;
    const int l = (i / NS) % NL;
    const int b = i / (NS * NL);
    out[i] = g_acc[(b * NS + s) * NL + l] * (1.f / TSTEPS) + b2[l];
}

// ---------------------------------------------------------------------------
extern "C" void kernel_launch(void* const* d_in, const int* in_sizes, int n_in,
                              void* d_out, int out_size)
{
    (void)in_sizes; (void)n_in; (void)out_size;
    const float* se = (const float*)d_in[0];
    const float* te = (const float*)d_in[1];
    const float* Wb = (const float*)d_in[2];
    const float* Wa = (const float*)d_in[3];
    const float* W1 = (const float*)d_in[4];
    const float* b1 = (const float*)d_in[5];
    const float* W2 = (const float*)d_in[6];
    const float* b2 = (const float*)d_in[7];
    float* out = (float*)d_out;

    float *apical, *bpart, *hpart;
    __nv_bfloat16 *Wah, *Wal, *Wbh, *Wbl, *W1h, *W1l, *sp16;
    cudaGetSymbolAddress((void**)&apical, g_apical);
    cudaGetSymbolAddress((void**)&bpart,  g_bpart);
    cudaGetSymbolAddress((void**)&hpart,  g_hpart);
    cudaGetSymbolAddress((void**)&Wah,    g_Wah);
    cudaGetSymbolAddress((void**)&Wal,    g_Wal);
    cudaGetSymbolAddress((void**)&Wbh,    g_Wbh);
    cudaGetSymbolAddress((void**)&Wbl,    g_Wbl);
    cudaGetSymbolAddress((void**)&W1h,    g_W1h);
    cudaGetSymbolAddress((void**)&W1l,    g_W1l);
    cudaGetSymbolAddress((void**)&sp16,   g_sp16);

    const int SMEM3 = 4 * 128 * BKT * 2 * NSTG;   // 98304
    const int SMEM2 = 3 * 128 * BKT * 2 * NSTG;   // 73728
    cudaFuncSetAttribute(hmma_fused<3>, cudaFuncAttributeMaxDynamicSharedMemorySize, SMEM3);
    cudaFuncSetAttribute(hmma_fused<2>, cudaFuncAttributeMaxDynamicSharedMemorySize, SMEM2);

    // weight hi/lo splits only (te/se split in-kernel now)
    split_bf16<<<(NF * NK / 4 + 255) / 256, 256>>>(Wa, Wah, Wal, NF * NK / 4);
    split_bf16<<<(NF * NK / 4 + 255) / 256, 256>>>(Wb, Wbh, Wbl, NF * NK / 4);
    split_bf16<<<(NH * NF / 4 + 255) / 256, 256>>>(W1, W1h, W1l, NH * NF / 4);

    init_state<<<(NBS * NF + 255) / 256, 256>>>();

    // basal: fp32-A fused-split HMMA, M=512 K=3136 N=512, split-K=7
    hmma_fused<3><<<dim3(NF / 128, (TSTEPS * NB) / 128, KSB), 256, SMEM3>>>(
        se, Wbh, Wbl, KCH_B, NK, NF, bpart, TSTEPS * NB);
    reduce_basal_mb<<<(NB * NF + 255) / 256, 256>>>();

    // apical: fp32-A fused-split HMMA, M=16384 N=512 K=3136, single sweep
    hmma_fused<3><<<dim3(NF / 128, (TSTEPS * NBS) / 128, 1), 256, SMEM3>>>(
        te, Wah, Wal, NK, NK, NF, apical, TSTEPS * NBS);

    for (int t = 0; t < TSTEPS; t++) {
        mc_spike<<<(NBS * NF / 4 + 255) / 256, 256>>>(t);
        // h = sp @ W1^T : sp exact bf16, W1 split => 2 products, split-K=2
        hmma_fused<2><<<dim3(NH / 128, NBS / 128, KSH), 256, SMEM2>>>(
            sp16, W1h, W1l, KCH_H, NF, NH, hpart, NBS);
        lif_out<<<(NBS * 32 + 255) / 256, 256>>>(b1, W2);
    }

    finalize<<<(NB * NL * NS + 255) / 256, 256>>>(b2, out);
}